// round 1
// baseline (speedup 1.0000x reference)
#include <cuda_runtime.h>
#include <math.h>

#define BB     16
#define CC     256
#define HH     64
#define WWID   64
#define PP     4096   // HH*WWID
#define TT     1024   // 32*32 pooled tokens
#define NHEADS 8
#define DHEAD  32

// ---------------- scratch (device globals; no allocs allowed) ----------------
__device__ float         g_pooled[BB*CC*TT];           // [b][c][t]
__device__ unsigned char g_idx   [BB*CC*TT];           // argmax 0..3
__device__ float         g_q   [BB*NHEADS*DHEAD*TT];   // [bh][dhi][t]
__device__ float         g_k   [BB*NHEADS*DHEAD*TT];
__device__ float         g_v   [BB*NHEADS*DHEAD*TT];
__device__ float         g_attn[BB*NHEADS*DHEAD*TT];   // [bh][dhi][t]
__device__ float         g_proj[BB*CC*TT];             // [b][c][t], pre-scaled by tanh(gamma)

// =====================================================================
// Kernel 1: 1x1 conv (feature reduce) + bias + 2x2 maxpool with indices
// Block: 64 oc x 128 px (2 image rows), grid (32 row-pairs, 4 ocT, 16 b)
// =====================================================================
__global__ __launch_bounds__(256) void k_fr_pool(
    const float* __restrict__ x, const float* __restrict__ frw,
    const float* __restrict__ frb)
{
    __shared__ float Xs[32][128];
    __shared__ float Ws[64][32];
    int tid = threadIdx.x;
    int hp = blockIdx.x, ocT = blockIdx.y, b = blockIdx.z;
    int oc0 = ocT * 64;
    int ocg = tid >> 5;       // 0..7 -> 8 oc each
    int pxg = tid & 31;       // 0..31 -> 4 px each

    float acc[8][4];
#pragma unroll
    for (int i = 0; i < 8; i++)
#pragma unroll
        for (int j = 0; j < 4; j++) acc[i][j] = 0.f;

    const float* xb = x + (size_t)b*CC*PP + hp*128;   // rows 2hp,2hp+1 contiguous

    for (int c0 = 0; c0 < CC; c0 += 32) {
#pragma unroll
        for (int j = 0; j < 4; j++) {
            int f = tid + j*256;              // float4 index 0..1023
            int k = f >> 5, c4 = f & 31;
            *(float4*)&Xs[k][c4*4] = *(const float4*)(xb + (size_t)(c0+k)*PP + c4*4);
        }
#pragma unroll
        for (int j = 0; j < 8; j++) {
            int f = tid + j*256;              // 0..2047
            int oc = f >> 5, k = f & 31;
            Ws[oc][k] = frw[(size_t)(oc0+oc)*CC + c0 + k];
        }
        __syncthreads();
#pragma unroll 8
        for (int k = 0; k < 32; k++) {
            float4 xv = *(const float4*)&Xs[k][pxg*4];
#pragma unroll
            for (int i = 0; i < 8; i++) {
                float w = Ws[ocg*8+i][k];     // broadcast within warp
                acc[i][0] = fmaf(w, xv.x, acc[i][0]);
                acc[i][1] = fmaf(w, xv.y, acc[i][1]);
                acc[i][2] = fmaf(w, xv.z, acc[i][2]);
                acc[i][3] = fmaf(w, xv.w, acc[i][3]);
            }
        }
        __syncthreads();
    }

    // pooling: thread pxg<16 holds row0 cols [4pxg..4pxg+3]; partner pxg^16 holds row1
    bool low = (pxg < 16);
#pragma unroll
    for (int i = 0; i < 8; i++) {
        int oc = oc0 + ocg*8 + i;
        float bi = frb[oc];
        float a0 = acc[i][0]+bi, a1 = acc[i][1]+bi;
        float a2 = acc[i][2]+bi, a3 = acc[i][3]+bi;
        float p0 = __shfl_xor_sync(0xffffffffu, a0, 16);
        float p1 = __shfl_xor_sync(0xffffffffu, a1, 16);
        float p2 = __shfl_xor_sync(0xffffffffu, a2, 16);
        float p3 = __shfl_xor_sync(0xffffffffu, a3, 16);
        if (low) {
            size_t base = ((size_t)b*CC + oc)*TT + hp*32 + pxg*2;
            // window order: (r0,c),(r0,c+1),(r1,c),(r1,c+1); first-max tie-break
            {   float best = a0; int am = 0;
                if (a1 > best) { best = a1; am = 1; }
                if (p0 > best) { best = p0; am = 2; }
                if (p1 > best) { best = p1; am = 3; }
                g_pooled[base] = best; g_idx[base] = (unsigned char)am; }
            {   float best = a2; int am = 0;
                if (a3 > best) { best = a3; am = 1; }
                if (p2 > best) { best = p2; am = 2; }
                if (p3 > best) { best = p3; am = 3; }
                g_pooled[base+1] = best; g_idx[base+1] = (unsigned char)am; }
        }
    }
}

// =====================================================================
// Kernel 2: QKV projection. pooled^T @ W for q,k,v sharing the A tile.
// Output layout [b*8+head][dhi][t], head = d%8, dhi = d/8.
// Grid (16 tT, 4 dT, 16 b), 256 thr, each 4t x 4d x 3 mats.
// =====================================================================
__global__ __launch_bounds__(256) void k_qkv(
    const float* __restrict__ wq, const float* __restrict__ wk,
    const float* __restrict__ wv)
{
    __shared__ float As[32][64];
    __shared__ float Bq[32][64], Bk[32][64], Bv[32][64];
    int tid = threadIdx.x;
    int t0 = blockIdx.x*64, d0 = blockIdx.y*64, b = blockIdx.z;
    int ng = tid & 15, mg = tid >> 4;

    float aq[4][4], ak[4][4], av[4][4];
#pragma unroll
    for (int i = 0; i < 4; i++)
#pragma unroll
        for (int j = 0; j < 4; j++) { aq[i][j]=0.f; ak[i][j]=0.f; av[i][j]=0.f; }

    const float* pb = g_pooled + (size_t)b*CC*TT;

    for (int c0 = 0; c0 < CC; c0 += 32) {
#pragma unroll
        for (int j = 0; j < 2; j++) {
            int f = tid + j*256;              // f4 idx 0..511
            int k = f >> 4, m4 = f & 15;
            *(float4*)&As[k][m4*4] = *(const float4*)(pb + (size_t)(c0+k)*TT + t0 + m4*4);
            *(float4*)&Bq[k][m4*4] = *(const float4*)(wq + (size_t)(c0+k)*CC + d0 + m4*4);
            *(float4*)&Bk[k][m4*4] = *(const float4*)(wk + (size_t)(c0+k)*CC + d0 + m4*4);
            *(float4*)&Bv[k][m4*4] = *(const float4*)(wv + (size_t)(c0+k)*CC + d0 + m4*4);
        }
        __syncthreads();
#pragma unroll 8
        for (int k = 0; k < 32; k++) {
            float4 a  = *(const float4*)&As[k][mg*4];
            float4 q4 = *(const float4*)&Bq[k][ng*4];
            float4 k4 = *(const float4*)&Bk[k][ng*4];
            float4 v4 = *(const float4*)&Bv[k][ng*4];
            float am[4] = {a.x,a.y,a.z,a.w};
            float qn[4] = {q4.x,q4.y,q4.z,q4.w};
            float kn[4] = {k4.x,k4.y,k4.z,k4.w};
            float vn[4] = {v4.x,v4.y,v4.z,v4.w};
#pragma unroll
            for (int mm = 0; mm < 4; mm++)
#pragma unroll
                for (int nn = 0; nn < 4; nn++) {
                    aq[mm][nn] = fmaf(am[mm], qn[nn], aq[mm][nn]);
                    ak[mm][nn] = fmaf(am[mm], kn[nn], ak[mm][nn]);
                    av[mm][nn] = fmaf(am[mm], vn[nn], av[mm][nn]);
                }
        }
        __syncthreads();
    }

#pragma unroll
    for (int nn = 0; nn < 4; nn++) {
        int d = d0 + ng*4 + nn;
        int head = d & 7, dhi = d >> 3;
        size_t base = (((size_t)b*NHEADS + head)*DHEAD + dhi)*TT + t0 + mg*4;
        *(float4*)&g_q[base] = make_float4(aq[0][nn], aq[1][nn], aq[2][nn], aq[3][nn]);
        *(float4*)&g_k[base] = make_float4(ak[0][nn], ak[1][nn], ak[2][nn], ak[3][nn]);
        *(float4*)&g_v[base] = make_float4(av[0][nn], av[1][nn], av[2][nn], av[3][nn]);
    }
}

// =====================================================================
// Kernel 3: flash attention. Block = (bh, 64 queries); 64-key chunks.
// S-stage: thread = 2 qi x 8 kj; O-stage: thread = 1 qo x 8 dhi.
// =====================================================================
__global__ __launch_bounds__(256) void k_attn()
{
    __shared__ float Qs[32][64];
    __shared__ float Ks[32][64];
    __shared__ float Vs[64][36];     // [kj][dhi], pad 36 (f4-aligned)
    __shared__ float Ps[64][65];     // [qi][kj], odd pad -> conflict-free qo reads
    __shared__ float m_s[64], l_s[64], al_s[64];

    int tid = threadIdx.x;
    int q0 = blockIdx.x*64; int bh = blockIdx.y;
    const float* Qg = g_q + (size_t)bh*DHEAD*TT;
    const float* Kg = g_k + (size_t)bh*DHEAD*TT;
    const float* Vg = g_v + (size_t)bh*DHEAD*TT;
    const float qscale = 0.17677669529663687f;  // 1/sqrt(32)

#pragma unroll
    for (int j = 0; j < 2; j++) {
        int f = tid + j*256;
        int dhi = f >> 4, t4 = f & 15;
        float4 v = *(const float4*)(Qg + (size_t)dhi*TT + q0 + t4*4);
        v.x *= qscale; v.y *= qscale; v.z *= qscale; v.w *= qscale;
        *(float4*)&Qs[dhi][t4*4] = v;
    }
    if (tid < 64) { m_s[tid] = -3.0e38f; l_s[tid] = 0.f; }

    float o[8];
#pragma unroll
    for (int d = 0; d < 8; d++) o[d] = 0.f;

    int qig = tid >> 3, kjg = tid & 7;   // S map: qi = qig*2+{0,1}, kj = kjg*8+{0..7}
    int qo  = tid & 63, dhg = tid >> 6;  // O map: dhi = dhg*8+{0..7}
    __syncthreads();

    for (int k0 = 0; k0 < TT; k0 += 64) {
#pragma unroll
        for (int j = 0; j < 2; j++) {
            int f = tid + j*256;
            int dhi = f >> 4, t4 = f & 15;
            *(float4*)&Ks[dhi][t4*4] = *(const float4*)(Kg + (size_t)dhi*TT + k0 + t4*4);
            float4 v = *(const float4*)(Vg + (size_t)dhi*TT + k0 + t4*4);
            Vs[t4*4+0][dhi] = v.x; Vs[t4*4+1][dhi] = v.y;
            Vs[t4*4+2][dhi] = v.z; Vs[t4*4+3][dhi] = v.w;
        }
        __syncthreads();

        // S = (Q/sqrt(dh))^T K
        float s[2][8];
#pragma unroll
        for (int i = 0; i < 2; i++)
#pragma unroll
            for (int j = 0; j < 8; j++) s[i][j] = 0.f;
#pragma unroll 8
        for (int dhi = 0; dhi < 32; dhi++) {
            float q0v = Qs[dhi][qig*2+0];
            float q1v = Qs[dhi][qig*2+1];
            float4 ka = *(const float4*)&Ks[dhi][kjg*8];
            float4 kb = *(const float4*)&Ks[dhi][kjg*8+4];
            float kv[8] = {ka.x,ka.y,ka.z,ka.w,kb.x,kb.y,kb.z,kb.w};
#pragma unroll
            for (int j = 0; j < 8; j++) {
                s[0][j] = fmaf(q0v, kv[j], s[0][j]);
                s[1][j] = fmaf(q1v, kv[j], s[1][j]);
            }
        }

        // online softmax update (reduction across 8 kjg lanes; in-warp)
        float mnew[2], alp[2], csum[2];
#pragma unroll
        for (int i = 0; i < 2; i++) {
            float m = s[i][0];
#pragma unroll
            for (int j = 1; j < 8; j++) m = fmaxf(m, s[i][j]);
            m = fmaxf(m, __shfl_xor_sync(0xffffffffu, m, 4));
            m = fmaxf(m, __shfl_xor_sync(0xffffffffu, m, 2));
            m = fmaxf(m, __shfl_xor_sync(0xffffffffu, m, 1));
            int qi = qig*2 + i;
            float mold = m_s[qi];
            mnew[i] = fmaxf(mold, m);
            alp[i]  = __expf(mold - mnew[i]);
            float cs = 0.f;
#pragma unroll
            for (int j = 0; j < 8; j++) {
                float p = __expf(s[i][j] - mnew[i]);
                Ps[qi][kjg*8+j] = p;
                cs += p;
            }
            cs += __shfl_xor_sync(0xffffffffu, cs, 4);
            cs += __shfl_xor_sync(0xffffffffu, cs, 2);
            cs += __shfl_xor_sync(0xffffffffu, cs, 1);
            csum[i] = cs;
        }
        if (kjg == 0) {
#pragma unroll
            for (int i = 0; i < 2; i++) {
                int qi = qig*2 + i;
                m_s[qi]  = mnew[i];
                l_s[qi]  = l_s[qi]*alp[i] + csum[i];
                al_s[qi] = alp[i];
            }
        }
        __syncthreads();

        // O = alpha*O + P V
        float alpha = al_s[qo];
#pragma unroll
        for (int d = 0; d < 8; d++) o[d] *= alpha;
#pragma unroll 4
        for (int kj = 0; kj < 64; kj++) {
            float p = Ps[qo][kj];
            float4 va = *(const float4*)&Vs[kj][dhg*8];
            float4 vb = *(const float4*)&Vs[kj][dhg*8+4];
            o[0] = fmaf(p, va.x, o[0]); o[1] = fmaf(p, va.y, o[1]);
            o[2] = fmaf(p, va.z, o[2]); o[3] = fmaf(p, va.w, o[3]);
            o[4] = fmaf(p, vb.x, o[4]); o[5] = fmaf(p, vb.y, o[5]);
            o[6] = fmaf(p, vb.z, o[6]); o[7] = fmaf(p, vb.w, o[7]);
        }
        __syncthreads();
    }

    float linv = 1.f / l_s[qo];
    float* Og = g_attn + (size_t)bh*DHEAD*TT;
#pragma unroll
    for (int d = 0; d < 8; d++)
        Og[(size_t)(dhg*8+d)*TT + q0 + qo] = o[d]*linv;
}

// =====================================================================
// Kernel 4: output projection (merged-heads @ wo), scaled by tanh(gamma).
// Output g_proj [b][c][t]. Grid (16 tT, 4 dT, 16 b).
// =====================================================================
__global__ __launch_bounds__(256) void k_proj(
    const float* __restrict__ wo, const float* __restrict__ gamma)
{
    __shared__ float As[32][64];
    __shared__ float Bs[32][64];
    int tid = threadIdx.x;
    int t0 = blockIdx.x*64, d0 = blockIdx.y*64, b = blockIdx.z;
    int ng = tid & 15, mg = tid >> 4;

    float acc[4][4];
#pragma unroll
    for (int i = 0; i < 4; i++)
#pragma unroll
        for (int j = 0; j < 4; j++) acc[i][j] = 0.f;

    for (int c0 = 0; c0 < CC; c0 += 32) {
#pragma unroll
        for (int j = 0; j < 2; j++) {
            int f = tid + j*256;
            int k = f >> 4, m4 = f & 15;
            int d = c0 + k;
            const float* src = g_attn + (((size_t)b*NHEADS + (d&7))*DHEAD + (d>>3))*TT + t0 + m4*4;
            *(float4*)&As[k][m4*4] = *(const float4*)src;
            *(float4*)&Bs[k][m4*4] = *(const float4*)(wo + (size_t)d*CC + d0 + m4*4);
        }
        __syncthreads();
#pragma unroll 8
        for (int k = 0; k < 32; k++) {
            float4 a  = *(const float4*)&As[k][mg*4];
            float4 bv = *(const float4*)&Bs[k][ng*4];
            float am[4] = {a.x,a.y,a.z,a.w};
            float bn[4] = {bv.x,bv.y,bv.z,bv.w};
#pragma unroll
            for (int mm = 0; mm < 4; mm++)
#pragma unroll
                for (int nn = 0; nn < 4; nn++)
                    acc[mm][nn] = fmaf(am[mm], bn[nn], acc[mm][nn]);
        }
        __syncthreads();
    }

    float tg = tanhf(gamma[0]);
#pragma unroll
    for (int nn = 0; nn < 4; nn++) {
        int d = d0 + ng*4 + nn;
        size_t base = ((size_t)b*CC + d)*TT + t0 + mg*4;
        *(float4*)&g_proj[base] =
            make_float4(acc[0][nn]*tg, acc[1][nn]*tg, acc[2][nn]*tg, acc[3][nn]*tg);
    }
}

// =====================================================================
// Kernel 5: conv3x3 (pad 1) + bias + unpool-add of g_proj (index-gated).
// Block: 32 oc x (4 rows x 64 cols); grid (16 rowT, 8 ocT, 16 b).
// =====================================================================
__global__ __launch_bounds__(256) void k_conv3_unpool(
    const float* __restrict__ x, const float* __restrict__ cw,
    const float* __restrict__ cb, float* __restrict__ out)
{
    __shared__ float Xs[8][6][68];   // ic x (4+2 halo rows) x (64+2 halo cols, padded)
    __shared__ float Ws[32][72];     // oc x (8 ic * 9 taps)
    int tid = threadIdx.x;
    int rowT = blockIdx.x, ocT = blockIdx.y, b = blockIdx.z;
    int oc0 = ocT*32;
    int ocg = tid >> 5;              // 0..7 -> 4 oc each
    int pxg = tid & 31;
    int row  = pxg >> 3;             // 0..3
    int colb = (pxg & 7) * 8;        // 0..56

    float acc[4][8];
#pragma unroll
    for (int i = 0; i < 4; i++)
#pragma unroll
        for (int j = 0; j < 8; j++) acc[i][j] = 0.f;

    for (int ic0 = 0; ic0 < CC; ic0 += 8) {
        for (int ic = 0; ic < 8; ic++) {
            const float* xc = x + ((size_t)b*CC + ic0 + ic)*PP;
            for (int idx = tid; idx < 6*66; idx += 256) {
                int rr = idx / 66, ccj = idx - rr*66;
                int gr = rowT*4 - 1 + rr, gc = ccj - 1;
                float v = 0.f;
                if ((unsigned)gr < 64u && (unsigned)gc < 64u)
                    v = xc[gr*64 + gc];
                Xs[ic][rr][ccj] = v;
            }
        }
        for (int f = tid; f < 32*72; f += 256) {
            int oc = f / 72, r = f - oc*72;
            Ws[oc][r] = cw[(size_t)(oc0+oc)*2304 + (size_t)ic0*9 + r];
        }
        __syncthreads();
#pragma unroll 1
        for (int ic = 0; ic < 8; ic++) {
#pragma unroll
            for (int kh = 0; kh < 3; kh++) {
                float xr[10];
#pragma unroll
                for (int t = 0; t < 10; t++) xr[t] = Xs[ic][row+kh][colb + t];
#pragma unroll
                for (int kw = 0; kw < 3; kw++) {
                    float w0 = Ws[ocg*4+0][ic*9+kh*3+kw];
                    float w1 = Ws[ocg*4+1][ic*9+kh*3+kw];
                    float w2 = Ws[ocg*4+2][ic*9+kh*3+kw];
                    float w3 = Ws[ocg*4+3][ic*9+kh*3+kw];
#pragma unroll
                    for (int j = 0; j < 8; j++) {
                        float xv = xr[kw+j];
                        acc[0][j] = fmaf(w0, xv, acc[0][j]);
                        acc[1][j] = fmaf(w1, xv, acc[1][j]);
                        acc[2][j] = fmaf(w2, xv, acc[2][j]);
                        acc[3][j] = fmaf(w3, xv, acc[3][j]);
                    }
                }
            }
        }
        __syncthreads();
    }

    int row_g = rowT*4 + row;
    int h2 = row_g >> 1;
    int subr = (row_g & 1) << 1;
#pragma unroll
    for (int i = 0; i < 4; i++) {
        int oc = oc0 + ocg*4 + i;
        float bias = cb[oc];
        size_t chan = (size_t)b*CC + oc;
        const unsigned char* idxp = g_idx  + chan*TT + (size_t)h2*32;
        const float*        projp = g_proj + chan*TT + (size_t)h2*32;
        float vout[8];
#pragma unroll
        for (int j = 0; j < 8; j++) {
            int wg = colb + j;
            float v = acc[i][j] + bias;
            int w2 = wg >> 1;
            if (idxp[w2] == (unsigned char)(subr | (wg & 1)))
                v += projp[w2];
            vout[j] = v;
        }
        float* op = out + chan*PP + (size_t)row_g*64 + colb;
        *(float4*)&op[0] = make_float4(vout[0], vout[1], vout[2], vout[3]);
        *(float4*)&op[4] = make_float4(vout[4], vout[5], vout[6], vout[7]);
    }
}

// =====================================================================
extern "C" void kernel_launch(void* const* d_in, const int* in_sizes, int n_in,
                              void* d_out, int out_size)
{
    const float* x      = (const float*)d_in[0];
    const float* conv_w = (const float*)d_in[1];
    const float* conv_b = (const float*)d_in[2];
    const float* fr_w   = (const float*)d_in[3];
    const float* fr_b   = (const float*)d_in[4];
    const float* wq     = (const float*)d_in[5];
    const float* wk     = (const float*)d_in[6];
    const float* wv     = (const float*)d_in[7];
    const float* wo     = (const float*)d_in[8];
    const float* gamma  = (const float*)d_in[9];
    float* out = (float*)d_out;

    k_fr_pool      <<<dim3(32, 4, BB),        256>>>(x, fr_w, fr_b);
    k_qkv          <<<dim3(16, 4, BB),        256>>>(wq, wk, wv);
    k_attn         <<<dim3(16, BB*NHEADS, 1), 256>>>();
    k_proj         <<<dim3(16, 4, BB),        256>>>(wo, gamma);
    k_conv3_unpool <<<dim3(16, 8, BB),        256>>>(x, conv_w, conv_b, out);
}